// round 14
// baseline (speedup 1.0000x reference)
#include <cuda_runtime.h>
#include <cuda_bf16.h>
#include <math.h>
#include <cstdint>

#define T_   64
#define P_   144
#define C_   1024
#define MID_ 256
#define ROWS (T_ * P_)   // 9216

#define ABUF_W 4096          // 128 rows x 32 words
#define BBUF_W 2048          // 64 rows x 32 words
#define SMEM_BYTES ((2 * ABUF_W + 2 * BBUF_W) * 4 + 256)

// ---------------- scratch (no allocations allowed) ----------------
__device__ __nv_bfloat16 g_pooled[ROWS * C_];  // 18.9 MB
__device__ __nv_bfloat16 g_q[ROWS * MID_];     //  4.7 MB
__device__ __nv_bfloat16 g_r[ROWS * C_];       // 18.9 MB
__device__ __nv_bfloat16 g_WT[MID_ * C_];      //  0.5 MB (Wq^T)
__device__ __nv_bfloat16 g_WkH[C_ * MID_];     //  0.5 MB (Wk)

__device__ __forceinline__ uint32_t smem_u32(const void* p) {
    uint32_t a;
    asm("{ .reg .u64 t; cvta.to.shared.u64 t, %1; cvt.u32.u64 %0, t; }"
        : "=r"(a) : "l"(p));
    return a;
}
__device__ __forceinline__ void cpasync16(uint32_t s, const void* g) {
    asm volatile("cp.async.cg.shared.global [%0], [%1], 16;" :: "r"(s), "l"(g));
}
#define CP_COMMIT() asm volatile("cp.async.commit_group;" ::: "memory")
#define CP_WAIT(N)  asm volatile("cp.async.wait_group %0;" :: "n"(N) : "memory")

__device__ __forceinline__ void mma_bf16(float& c0, float& c1, float& c2, float& c3,
                                         uint32_t a0, uint32_t a1, uint32_t a2, uint32_t a3,
                                         uint32_t b0, uint32_t b1) {
    asm volatile(
        "mma.sync.aligned.m16n8k16.row.col.f32.bf16.bf16.f32 "
        "{%0,%1,%2,%3}, {%4,%5,%6,%7}, {%8,%9}, {%0,%1,%2,%3};"
        : "+f"(c0), "+f"(c1), "+f"(c2), "+f"(c3)
        : "r"(a0), "r"(a1), "r"(a2), "r"(a3), "r"(b0), "r"(b1));
}

// ---------------- K1: 2x2 window average pool -> bf16 ----------------
__global__ void pool_kernel(const float* __restrict__ x) {
    int row = blockIdx.x;
    int t = row / P_, p = row % P_;
    int i = p / 12, j = p % 12;
    const float* base = x + ((size_t)t * 576 + (size_t)(2 * i) * 24 + 2 * j) * C_;
    int c = threadIdx.x * 4;
    float4 a = *(const float4*)(base + c);
    float4 b = *(const float4*)(base + C_ + c);
    float4 d = *(const float4*)(base + 24 * C_ + c);
    float4 e = *(const float4*)(base + 25 * C_ + c);
    __nv_bfloat162 o0 = __floats2bfloat162_rn(0.25f * ((a.x + b.x) + (d.x + e.x)),
                                              0.25f * ((a.y + b.y) + (d.y + e.y)));
    __nv_bfloat162 o1 = __floats2bfloat162_rn(0.25f * ((a.z + b.z) + (d.z + e.z)),
                                              0.25f * ((a.w + b.w) + (d.w + e.w)));
    uint2 pack = make_uint2(*(uint32_t*)&o0, *(uint32_t*)&o1);
    *(uint2*)(g_pooled + (size_t)row * C_ + c) = pack;
}

// ---------------- K2a: transpose Wq [1024,256] -> WT bf16 [256,1024] ----------
__global__ void transpose_w(const float* __restrict__ W) {
    __shared__ float s[32][33];
    int c0 = blockIdx.x * 32;
    int d0 = blockIdx.y * 32;
    int tx = threadIdx.x, ty = threadIdx.y;  // 32 x 8
#pragma unroll
    for (int u = 0; u < 32; u += 8)
        s[ty + u][tx] = W[(size_t)(c0 + ty + u) * MID_ + d0 + tx];
    __syncthreads();
#pragma unroll
    for (int u = 0; u < 32; u += 8)
        g_WT[(size_t)(d0 + ty + u) * C_ + c0 + tx] = __float2bfloat16(s[tx][ty + u]);
}

// ---------------- K2b: Wk -> bf16 copy ----------------
__global__ void cvt_wk(const float* __restrict__ Wk) {
    int i = blockIdx.x * 256 + threadIdx.x;
    float4 v = ((const float4*)Wk)[i];
    __nv_bfloat162 o0 = __floats2bfloat162_rn(v.x, v.y);
    __nv_bfloat162 o1 = __floats2bfloat162_rn(v.z, v.w);
    *(uint2*)(g_WkH + (size_t)i * 4) = make_uint2(*(uint32_t*)&o0, *(uint32_t*)&o1);
}

// ====== bf16 m16n8k16 GEMM: BM=128, BN=64, BK=64, 256 thr (8 warps, 4m x 2n) ===
// D[M,N] = A[M,K] @ B[N,K]^T (+bias), bf16 in, f32 acc, bf16 out.
// Warp tile 32x32 (2 mt x 4 nt). cp.async 2-stage double buffer.
// Smem unit = 32-bit word (2 bf16); tile row = 32 words (64 bf16).
// Word (row,kw) at row*32 + (kw ^ ((row&7)<<2)).
template <bool BIAS>
__global__ void __launch_bounds__(256)
gemm_bf16(const __nv_bfloat16* __restrict__ A, const __nv_bfloat16* __restrict__ B,
          const float* __restrict__ bias, __nv_bfloat16* __restrict__ Cout,
          const int N, const int K) {
    extern __shared__ uint32_t smem[];
    uint32_t* As0 = smem;                    // 2 x ABUF_W
    uint32_t* Bs0 = smem + 2 * ABUF_W;       // 2 x BBUF_W
    float* sBias = (float*)(smem + 2 * ABUF_W + 2 * BBUF_W);

    const int tid = threadIdx.x;
    const int lane = tid & 31, wid = tid >> 5;   // 8 warps
    const int warp_m = wid >> 1, warp_n = wid & 1;
    const int bm = blockIdx.y * 128, bn = blockIdx.x * 64;

    if (BIAS && tid < 64) sBias[tid] = bias[bn + tid];

    const int g = lane >> 2, tk = lane & 3;
    const int sw = g << 2;

    // staging: 8 x 16B columns over 64-elem K-chunk, 32-row strides
    const int lcol = tid & 7;     // 16B column
    const int lrow = tid >> 3;    // 0..31

    const __nv_bfloat16* ag = A + (size_t)(bm + lrow) * K + lcol * 8;
    const __nv_bfloat16* bg = B + (size_t)(bn + lrow) * K + lcol * 8;

    uint32_t aoff[4], boff[2];
#pragma unroll
    for (int it = 0; it < 4; it++) {
        int row = lrow + it * 32;
        aoff[it] = 4u * (uint32_t)(row * 32 + ((lcol * 4) ^ ((row & 7) << 2)));
    }
#pragma unroll
    for (int it = 0; it < 2; it++) {
        int row = lrow + it * 32;
        boff[it] = 4u * (uint32_t)(row * 32 + ((lcol * 4) ^ ((row & 7) << 2)));
    }
    const uint32_t uA[2] = { smem_u32(As0), smem_u32(As0 + ABUF_W) };
    const uint32_t uB[2] = { smem_u32(Bs0), smem_u32(Bs0 + BBUF_W) };

    float acc[2][4][4];
#pragma unroll
    for (int i = 0; i < 2; i++)
#pragma unroll
        for (int j = 0; j < 4; j++)
#pragma unroll
            for (int f = 0; f < 4; f++) acc[i][j][f] = 0.0f;

#define STAGE(BUF, K0)                                                         \
    {                                                                          \
        const int _k0 = (K0);                                                  \
        const uint32_t _ua = uA[BUF], _ub = uB[BUF];                           \
        _Pragma("unroll")                                                      \
        for (int it = 0; it < 4; it++)                                         \
            cpasync16(_ua + aoff[it], ag + (size_t)it * 32 * K + _k0);         \
        _Pragma("unroll")                                                      \
        for (int it = 0; it < 2; it++)                                         \
            cpasync16(_ub + boff[it], bg + (size_t)it * 32 * K + _k0);         \
    }

    STAGE(0, 0)
    CP_COMMIT();

    const int nch = K >> 6;   // 64 elems per chunk
    for (int ck = 0; ck < nch; ck++) {
        const int buf = ck & 1;
        const bool more = (ck + 1) < nch;
        if (more) {
            STAGE(buf ^ 1, (ck + 1) << 6)
            CP_COMMIT();
            CP_WAIT(1);
        } else {
            CP_WAIT(0);
        }
        __syncthreads();

        const uint32_t* Ab = As0 + buf * ABUF_W;
        const uint32_t* Bb = Bs0 + buf * BBUF_W;
#pragma unroll
        for (int ks = 0; ks < 4; ks++) {
            const int kx  = (ks * 8 + tk) ^ sw;
            const int kx4 = kx ^ 4;

            uint32_t af[2][4];
#pragma unroll
            for (int mt = 0; mt < 2; mt++) {
                int r = warp_m * 32 + mt * 16 + g;
                af[mt][0] = Ab[r * 32 + kx];
                af[mt][1] = Ab[(r + 8) * 32 + kx];
                af[mt][2] = Ab[r * 32 + kx4];
                af[mt][3] = Ab[(r + 8) * 32 + kx4];
            }
            uint32_t bf[4][2];
#pragma unroll
            for (int nt = 0; nt < 4; nt++) {
                int n = warp_n * 32 + nt * 8 + g;
                bf[nt][0] = Bb[n * 32 + kx];
                bf[nt][1] = Bb[n * 32 + kx4];
            }
#pragma unroll
            for (int mt = 0; mt < 2; mt++)
#pragma unroll
                for (int nt = 0; nt < 4; nt++)
                    mma_bf16(acc[mt][nt][0], acc[mt][nt][1],
                             acc[mt][nt][2], acc[mt][nt][3],
                             af[mt][0], af[mt][1], af[mt][2], af[mt][3],
                             bf[nt][0], bf[nt][1]);
        }
        __syncthreads();
    }
#undef STAGE

    // epilogue: bf16 out
#pragma unroll
    for (int mt = 0; mt < 2; mt++) {
#pragma unroll
        for (int nt = 0; nt < 4; nt++) {
            int r = bm + warp_m * 32 + mt * 16 + g;
            int cbase = warp_n * 32 + nt * 8 + tk * 2;
            float b0 = BIAS ? sBias[cbase] : 0.0f;
            float b1 = BIAS ? sBias[cbase + 1] : 0.0f;
            int cg = bn + cbase;
            *(__nv_bfloat162*)(Cout + (size_t)r * N + cg) =
                __floats2bfloat162_rn(acc[mt][nt][0] + b0, acc[mt][nt][1] + b1);
            *(__nv_bfloat162*)(Cout + (size_t)(r + 8) * N + cg) =
                __floats2bfloat162_rn(acc[mt][nt][2] + b0, acc[mt][nt][3] + b1);
        }
    }
}

// ---------------- K5: attention dots + softmax + weighted epilogue ----------------
__global__ void attn_kernel(const float* __restrict__ x, const float* __restrict__ bk,
                            float* __restrict__ out) {
    int row = blockIdx.x;
    int t = row / P_, p = row % P_;
    int i = p / 12, j = p % 12;
    const float* xb = x + ((size_t)t * 576 + (size_t)(2 * i) * 24 + 2 * j) * C_;
    const __nv_bfloat16* rr = g_r + (size_t)row * C_;
    int tid = threadIdx.x;
    int c = tid * 4;

    const __nv_bfloat162* rp = (const __nv_bfloat162*)(rr + c);
    float2 r01 = __bfloat1622float2(rp[0]);
    float2 r23 = __bfloat1622float2(rp[1]);
    float4 rv = make_float4(r01.x, r01.y, r23.x, r23.y);

    float4 x0 = *(const float4*)(xb + c);
    float4 x1 = *(const float4*)(xb + C_ + c);
    float4 x2 = *(const float4*)(xb + 24 * C_ + c);
    float4 x3 = *(const float4*)(xb + 25 * C_ + c);

    float s0 = rv.x * x0.x + rv.y * x0.y + rv.z * x0.z + rv.w * x0.w;
    float s1 = rv.x * x1.x + rv.y * x1.y + rv.z * x1.z + rv.w * x1.w;
    float s2 = rv.x * x2.x + rv.y * x2.y + rv.z * x2.z + rv.w * x2.w;
    float s3 = rv.x * x3.x + rv.y * x3.y + rv.z * x3.z + rv.w * x3.w;
    float qb = __bfloat162float(g_q[(size_t)row * MID_ + tid]) * bk[tid];

#pragma unroll
    for (int off = 16; off > 0; off >>= 1) {
        s0 += __shfl_down_sync(0xffffffff, s0, off);
        s1 += __shfl_down_sync(0xffffffff, s1, off);
        s2 += __shfl_down_sync(0xffffffff, s2, off);
        s3 += __shfl_down_sync(0xffffffff, s3, off);
        qb += __shfl_down_sync(0xffffffff, qb, off);
    }

    __shared__ float red[8][5];
    __shared__ float coef[4];
    int lane = tid & 31, warp = tid >> 5;
    if (lane == 0) {
        red[warp][0] = s0; red[warp][1] = s1; red[warp][2] = s2;
        red[warp][3] = s3; red[warp][4] = qb;
    }
    __syncthreads();
    if (tid == 0) {
        float S[5] = {0.f, 0.f, 0.f, 0.f, 0.f};
#pragma unroll
        for (int w = 0; w < 8; w++)
#pragma unroll
            for (int k = 0; k < 5; k++) S[k] += red[w][k];
        const float scale = 0.0625f;  // 1/sqrt(256)
        float l0 = (S[0] + S[4]) * scale;
        float l1 = (S[1] + S[4]) * scale;
        float l2 = (S[2] + S[4]) * scale;
        float l3 = (S[3] + S[4]) * scale;
        float m = fmaxf(fmaxf(l0, l1), fmaxf(l2, l3));
        float e0 = expf(l0 - m), e1 = expf(l1 - m);
        float e2 = expf(l2 - m), e3 = expf(l3 - m);
        float inv = 1.0f / (e0 + e1 + e2 + e3);
        coef[0] = 0.25f + e0 * inv;
        coef[1] = 0.25f + e1 * inv;
        coef[2] = 0.25f + e2 * inv;
        coef[3] = 0.25f + e3 * inv;
    }
    __syncthreads();
    float c0 = coef[0], c1 = coef[1], c2 = coef[2], c3 = coef[3];
    float4 o;
    o.x = c0 * x0.x + c1 * x1.x + c2 * x2.x + c3 * x3.x;
    o.y = c0 * x0.y + c1 * x1.y + c2 * x2.y + c3 * x3.y;
    o.z = c0 * x0.z + c1 * x1.z + c2 * x2.z + c3 * x3.z;
    o.w = c0 * x0.w + c1 * x1.w + c2 * x2.w + c3 * x3.w;
    *(float4*)(out + (size_t)row * C_ + c) = o;
}

// ---------------- launch ----------------
extern "C" void kernel_launch(void* const* d_in, const int* in_sizes, int n_in,
                              void* d_out, int out_size) {
    const float* x  = (const float*)d_in[0];  // [64, 576, 1024]
    const float* Wq = (const float*)d_in[1];  // [1024, 256]
    const float* bq = (const float*)d_in[2];  // [256]
    const float* Wk = (const float*)d_in[3];  // [1024, 256]
    const float* bk = (const float*)d_in[4];  // [256]
    float* out = (float*)d_out;               // [64, 144, 1024]

    __nv_bfloat16 *pooled, *q, *r, *wt, *wkh;
    cudaGetSymbolAddress((void**)&pooled, g_pooled);
    cudaGetSymbolAddress((void**)&q, g_q);
    cudaGetSymbolAddress((void**)&r, g_r);
    cudaGetSymbolAddress((void**)&wt, g_WT);
    cudaGetSymbolAddress((void**)&wkh, g_WkH);

    static int smem_set = 0;
    if (!smem_set) {
        cudaFuncSetAttribute(gemm_bf16<true>,
                             cudaFuncAttributeMaxDynamicSharedMemorySize, SMEM_BYTES);
        cudaFuncSetAttribute(gemm_bf16<false>,
                             cudaFuncAttributeMaxDynamicSharedMemorySize, SMEM_BYTES);
        smem_set = 1;
    }

    pool_kernel<<<ROWS, 256>>>(x);
    transpose_w<<<dim3(32, 8), dim3(32, 8)>>>(Wq);
    cvt_wk<<<256, 256>>>(Wk);
    // q[9216,256] = pooled @ Wq + bq   (bf16 mma; B = Wq^T rows K-major)
    gemm_bf16<true><<<dim3(MID_ / 64, ROWS / 128), 256, SMEM_BYTES>>>(
        pooled, wt, bq, q, MID_, C_);
    // r[9216,1024] = q @ Wk^T          (bf16 mma; B = Wk as-is, K-major rows)
    gemm_bf16<false><<<dim3(C_ / 64, ROWS / 128), 256, SMEM_BYTES>>>(
        q, wkh, nullptr, r, C_, MID_);
    attn_kernel<<<ROWS, 256>>>(x, bk, out);
}

// round 15
// speedup vs baseline: 1.0066x; 1.0066x over previous
#include <cuda_runtime.h>
#include <cuda_bf16.h>
#include <math.h>
#include <cstdint>

#define T_   64
#define P_   144
#define C_   1024
#define MID_ 256
#define ROWS (T_ * P_)   // 9216

// ---- fused gemm1 smem layout (dynamic) ----
#define F_AW   2048                      // A: 64 rows x 32 words (single buffer)
#define F_BW   8192                      // B: 256 rows x 32 words (per buffer)
#define F_SMEM_BYTES ((F_AW + 2 * F_BW) * 4 + MID_ * 4)

// ---------------- scratch (no allocations allowed) ----------------
__device__ __nv_bfloat16 g_q[ROWS * MID_];     //  4.7 MB
__device__ __nv_bfloat16 g_r[ROWS * C_];       // 18.9 MB
__device__ __nv_bfloat16 g_WT[MID_ * C_];      //  0.5 MB (Wq^T)
__device__ __nv_bfloat16 g_WkH[C_ * MID_];     //  0.5 MB (Wk)

__device__ __forceinline__ uint32_t smem_u32(const void* p) {
    uint32_t a;
    asm("{ .reg .u64 t; cvta.to.shared.u64 t, %1; cvt.u32.u64 %0, t; }"
        : "=r"(a) : "l"(p));
    return a;
}
__device__ __forceinline__ void cpasync16(uint32_t s, const void* g) {
    asm volatile("cp.async.cg.shared.global [%0], [%1], 16;" :: "r"(s), "l"(g));
}
#define CP_COMMIT() asm volatile("cp.async.commit_group;" ::: "memory")
#define CP_WAIT(N)  asm volatile("cp.async.wait_group %0;" :: "n"(N) : "memory")

__device__ __forceinline__ void mma_bf16(float& c0, float& c1, float& c2, float& c3,
                                         uint32_t a0, uint32_t a1, uint32_t a2, uint32_t a3,
                                         uint32_t b0, uint32_t b1) {
    asm volatile(
        "mma.sync.aligned.m16n8k16.row.col.f32.bf16.bf16.f32 "
        "{%0,%1,%2,%3}, {%4,%5,%6,%7}, {%8,%9}, {%0,%1,%2,%3};"
        : "+f"(c0), "+f"(c1), "+f"(c2), "+f"(c3)
        : "r"(a0), "r"(a1), "r"(a2), "r"(a3), "r"(b0), "r"(b1));
}
__device__ __forceinline__ uint32_t pack_bf16x2(float a, float b) {
    __nv_bfloat162 h = __floats2bfloat162_rn(a, b);
    return *(uint32_t*)&h;
}

// ---------------- K2a: transpose Wq [1024,256] -> WT bf16 [256,1024] ----------
__global__ void transpose_w(const float* __restrict__ W) {
    __shared__ float s[32][33];
    int c0 = blockIdx.x * 32;
    int d0 = blockIdx.y * 32;
    int tx = threadIdx.x, ty = threadIdx.y;  // 32 x 8
#pragma unroll
    for (int u = 0; u < 32; u += 8)
        s[ty + u][tx] = W[(size_t)(c0 + ty + u) * MID_ + d0 + tx];
    __syncthreads();
#pragma unroll
    for (int u = 0; u < 32; u += 8)
        g_WT[(size_t)(d0 + ty + u) * C_ + c0 + tx] = __float2bfloat16(s[tx][ty + u]);
}

// ---------------- K2b: Wk -> bf16 copy ----------------
__global__ void cvt_wk(const float* __restrict__ Wk) {
    int i = blockIdx.x * 256 + threadIdx.x;
    float4 v = ((const float4*)Wk)[i];
    __nv_bfloat162 o0 = __floats2bfloat162_rn(v.x, v.y);
    __nv_bfloat162 o1 = __floats2bfloat162_rn(v.z, v.w);
    *(uint2*)(g_WkH + (size_t)i * 4) = make_uint2(*(uint32_t*)&o0, *(uint32_t*)&o1);
}

// ====== GEMM1 + pool fused: q[9216,256] = pool2x2(x) @ Wq + bq =================
// BM=64, BN=256 (= full MID so x is read exactly once), BK=64. 256 thr = 8 warps
// (2 warp_m x 4 warp_n), warp tile 32x64 (2 mt x 8 nt), acc 64 regs.
// A: LDG 4 window rows (fp32) -> avg -> bf16 -> STS, single buffer.
// B: Wq^T rows (bf16, L2-resident) via cp.async double buffer.
// Smem word (row,kw) at row*32 + (kw ^ ((row&7)<<2)).
__global__ void __launch_bounds__(256)
gemm1_fused(const float* __restrict__ x, const __nv_bfloat16* __restrict__ B,
            const float* __restrict__ bias, __nv_bfloat16* __restrict__ Cout) {
    const int K = C_, N = MID_;
    extern __shared__ uint32_t smem[];
    uint32_t* As = smem;                      // F_AW
    uint32_t* Bs0 = smem + F_AW;              // 2 x F_BW
    float* sBias = (float*)(smem + F_AW + 2 * F_BW);

    const int tid = threadIdx.x;
    const int lane = tid & 31, wid = tid >> 5;
    const int warp_m = wid >> 2, warp_n = wid & 3;
    const int bm = blockIdx.x * 64;

    if (tid < MID_) sBias[tid] = bias[tid];

    const int g = lane >> 2, tk = lane & 3;
    const int sw = g << 2;

    const int lcol = tid & 7;     // 16B column (8 elems)
    const int lrow = tid >> 3;    // 0..31

    // ---- A (pool) staging: 2 slots/thread, rows lrow, lrow+32 ----
    const float* aptr[2];
    uint32_t aoff[2];
#pragma unroll
    for (int it = 0; it < 2; it++) {
        int row = lrow + it * 32;
        int rg = bm + row;
        int t = rg / P_, p = rg % P_;
        int i = p / 12, j = p % 12;
        aptr[it] = x + ((size_t)t * 576 + (size_t)(2 * i) * 24 + 2 * j) * C_
                     + lcol * 8;
        aoff[it] = (uint32_t)(row * 32 + ((lcol * 4) ^ ((row & 7) << 2)));
    }
    // ---- B staging: 8 slots/thread, rows lrow + it*32 (256 rows total) ----
    const __nv_bfloat16* bg = B + (size_t)lrow * K + lcol * 8;
    uint32_t boff[8];
#pragma unroll
    for (int it = 0; it < 8; it++) {
        int row = lrow + it * 32;
        boff[it] = 4u * (uint32_t)(row * 32 + ((lcol * 4) ^ ((row & 7) << 2)));
    }
    const uint32_t uB[2] = { smem_u32(Bs0), smem_u32(Bs0 + F_BW) };

    float acc[2][8][4];
#pragma unroll
    for (int i = 0; i < 2; i++)
#pragma unroll
        for (int j = 0; j < 8; j++)
#pragma unroll
            for (int f = 0; f < 4; f++) acc[i][j][f] = 0.0f;

#define STAGE_B(BUF, K0)                                                       \
    {                                                                          \
        const int _k0 = (K0);                                                  \
        const uint32_t _ub = uB[BUF];                                          \
        _Pragma("unroll")                                                      \
        for (int it = 0; it < 8; it++)                                         \
            cpasync16(_ub + boff[it], bg + (size_t)it * 32 * K + _k0);         \
    }

    STAGE_B(0, 0)
    CP_COMMIT();

    const int nch = K >> 6;   // 16 chunks
    for (int ck = 0; ck < nch; ck++) {
        const int buf = ck & 1;
        const bool more = (ck + 1) < nch;
        const int k0 = ck << 6;
        if (more) {
            STAGE_B(buf ^ 1, (ck + 1) << 6)
            CP_COMMIT();
        }

        // A: pool 4 window rows -> bf16 -> STS (2 slots)
#pragma unroll
        for (int it = 0; it < 2; it++) {
            const float* p = aptr[it] + k0;
            float4 u0 = *(const float4*)(p);
            float4 u1 = *(const float4*)(p + 4);
            float4 v0 = *(const float4*)(p + C_);
            float4 v1 = *(const float4*)(p + C_ + 4);
            float4 w0 = *(const float4*)(p + 24 * C_);
            float4 w1 = *(const float4*)(p + 24 * C_ + 4);
            float4 z0 = *(const float4*)(p + 25 * C_);
            float4 z1 = *(const float4*)(p + 25 * C_ + 4);
            uint4 pk;
            pk.x = pack_bf16x2(0.25f * ((u0.x + v0.x) + (w0.x + z0.x)),
                               0.25f * ((u0.y + v0.y) + (w0.y + z0.y)));
            pk.y = pack_bf16x2(0.25f * ((u0.z + v0.z) + (w0.z + z0.z)),
                               0.25f * ((u0.w + v0.w) + (w0.w + z0.w)));
            pk.z = pack_bf16x2(0.25f * ((u1.x + v1.x) + (w1.x + z1.x)),
                               0.25f * ((u1.y + v1.y) + (w1.y + z1.y)));
            pk.w = pack_bf16x2(0.25f * ((u1.z + v1.z) + (w1.z + z1.z)),
                               0.25f * ((u1.w + v1.w) + (w1.w + z1.w)));
            *(uint4*)&As[aoff[it]] = pk;
        }

        if (more) CP_WAIT(1); else CP_WAIT(0);
        __syncthreads();

        const uint32_t* Bb = Bs0 + buf * F_BW;
#pragma unroll
        for (int ks = 0; ks < 4; ks++) {
            const int kx  = (ks * 8 + tk) ^ sw;
            const int kx4 = kx ^ 4;

            uint32_t af[2][4];
#pragma unroll
            for (int mt = 0; mt < 2; mt++) {
                int r = warp_m * 32 + mt * 16 + g;
                af[mt][0] = As[r * 32 + kx];
                af[mt][1] = As[(r + 8) * 32 + kx];
                af[mt][2] = As[r * 32 + kx4];
                af[mt][3] = As[(r + 8) * 32 + kx4];
            }
            uint32_t bf[8][2];
#pragma unroll
            for (int nt = 0; nt < 8; nt++) {
                int n = warp_n * 64 + nt * 8 + g;
                bf[nt][0] = Bb[n * 32 + kx];
                bf[nt][1] = Bb[n * 32 + kx4];
            }
#pragma unroll
            for (int mt = 0; mt < 2; mt++)
#pragma unroll
                for (int nt = 0; nt < 8; nt++)
                    mma_bf16(acc[mt][nt][0], acc[mt][nt][1],
                             acc[mt][nt][2], acc[mt][nt][3],
                             af[mt][0], af[mt][1], af[mt][2], af[mt][3],
                             bf[nt][0], bf[nt][1]);
        }
        __syncthreads();   // protect As (and retire Bb) before next stage
    }
#undef STAGE_B

    // epilogue: q bf16 out [64 x 256]
#pragma unroll
    for (int mt = 0; mt < 2; mt++) {
#pragma unroll
        for (int nt = 0; nt < 8; nt++) {
            int r = bm + warp_m * 32 + mt * 16 + g;
            int cbase = warp_n * 64 + nt * 8 + tk * 2;
            float b0 = sBias[cbase], b1 = sBias[cbase + 1];
            *(__nv_bfloat162*)(Cout + (size_t)r * N + cbase) =
                __floats2bfloat162_rn(acc[mt][nt][0] + b0, acc[mt][nt][1] + b1);
            *(__nv_bfloat162*)(Cout + (size_t)(r + 8) * N + cbase) =
                __floats2bfloat162_rn(acc[mt][nt][2] + b0, acc[mt][nt][3] + b1);
        }
    }
}

// ====== GEMM2 (R11-proven): bf16 m16n8k16, BM=128, BN=64, BK=64, 128 thr =======
__global__ void __launch_bounds__(128)
gemm2_bf16(const __nv_bfloat16* __restrict__ A, const __nv_bfloat16* __restrict__ B,
           __nv_bfloat16* __restrict__ Cout, const int N, const int K) {
    __shared__ uint32_t As[2][128 * 32];
    __shared__ uint32_t Bs[2][64 * 32];

    const int tid = threadIdx.x;
    const int lane = tid & 31, wid = tid >> 5;
    const int warp_m = wid >> 1, warp_n = wid & 1;
    const int bm = blockIdx.y * 128, bn = blockIdx.x * 64;

    const int g = lane >> 2, tk = lane & 3;
    const int sw = g << 2;

    const int lcol = tid & 7;
    const int lrow = tid >> 3;

    const __nv_bfloat16* ag = A + (size_t)(bm + lrow) * K + lcol * 8;
    const __nv_bfloat16* bg = B + (size_t)(bn + lrow) * K + lcol * 8;

    uint32_t aoff[8], boff[4];
#pragma unroll
    for (int it = 0; it < 8; it++) {
        int row = lrow + it * 16;
        aoff[it] = 4u * (uint32_t)(row * 32 + ((lcol * 4) ^ ((row & 7) << 2)));
    }
#pragma unroll
    for (int it = 0; it < 4; it++) {
        int row = lrow + it * 16;
        boff[it] = 4u * (uint32_t)(row * 32 + ((lcol * 4) ^ ((row & 7) << 2)));
    }
    const uint32_t uAb[2] = { smem_u32(As[0]), smem_u32(As[1]) };
    const uint32_t uBb[2] = { smem_u32(Bs[0]), smem_u32(Bs[1]) };

    float acc[4][4][4];
#pragma unroll
    for (int i = 0; i < 4; i++)
#pragma unroll
        for (int j = 0; j < 4; j++)
#pragma unroll
            for (int f = 0; f < 4; f++) acc[i][j][f] = 0.0f;

#define STAGE(BUF, K0)                                                         \
    {                                                                          \
        const int _k0 = (K0);                                                  \
        const uint32_t _ua = uAb[BUF], _ub = uBb[BUF];                         \
        _Pragma("unroll")                                                      \
        for (int it = 0; it < 8; it++)                                         \
            cpasync16(_ua + aoff[it], ag + (size_t)it * 16 * K + _k0);         \
        _Pragma("unroll")                                                      \
        for (int it = 0; it < 4; it++)                                         \
            cpasync16(_ub + boff[it], bg + (size_t)it * 16 * K + _k0);         \
    }

    STAGE(0, 0)
    CP_COMMIT();

    const int nch = K >> 6;
    for (int ck = 0; ck < nch; ck++) {
        const int buf = ck & 1;
        const bool more = (ck + 1) < nch;
        if (more) {
            STAGE(buf ^ 1, (ck + 1) << 6)
            CP_COMMIT();
            CP_WAIT(1);
        } else {
            CP_WAIT(0);
        }
        __syncthreads();

        const uint32_t* Ab = As[buf];
        const uint32_t* Bb = Bs[buf];
#pragma unroll
        for (int ks = 0; ks < 4; ks++) {
            const int kx  = (ks * 8 + tk) ^ sw;
            const int kx4 = kx ^ 4;

            uint32_t af[4][4];
#pragma unroll
            for (int mt = 0; mt < 4; mt++) {
                int r = warp_m * 64 + mt * 16 + g;
                af[mt][0] = Ab[r * 32 + kx];
                af[mt][1] = Ab[(r + 8) * 32 + kx];
                af[mt][2] = Ab[r * 32 + kx4];
                af[mt][3] = Ab[(r + 8) * 32 + kx4];
            }
            uint32_t bf[4][2];
#pragma unroll
            for (int nt = 0; nt < 4; nt++) {
                int n = warp_n * 32 + nt * 8 + g;
                bf[nt][0] = Bb[n * 32 + kx];
                bf[nt][1] = Bb[n * 32 + kx4];
            }
#pragma unroll
            for (int mt = 0; mt < 4; mt++)
#pragma unroll
                for (int nt = 0; nt < 4; nt++)
                    mma_bf16(acc[mt][nt][0], acc[mt][nt][1],
                             acc[mt][nt][2], acc[mt][nt][3],
                             af[mt][0], af[mt][1], af[mt][2], af[mt][3],
                             bf[nt][0], bf[nt][1]);
        }
        __syncthreads();
    }
#undef STAGE

#pragma unroll
    for (int mt = 0; mt < 4; mt++) {
#pragma unroll
        for (int nt = 0; nt < 4; nt++) {
            int r = bm + warp_m * 64 + mt * 16 + g;
            int cg = bn + warp_n * 32 + nt * 8 + tk * 2;
            *(__nv_bfloat162*)(Cout + (size_t)r * N + cg) =
                __floats2bfloat162_rn(acc[mt][nt][0], acc[mt][nt][1]);
            *(__nv_bfloat162*)(Cout + (size_t)(r + 8) * N + cg) =
                __floats2bfloat162_rn(acc[mt][nt][2], acc[mt][nt][3]);
        }
    }
}

// ---------------- attention dots + softmax + weighted epilogue ----------------
__global__ void attn_kernel(const float* __restrict__ x, const float* __restrict__ bk,
                            float* __restrict__ out) {
    int row = blockIdx.x;
    int t = row / P_, p = row % P_;
    int i = p / 12, j = p % 12;
    const float* xb = x + ((size_t)t * 576 + (size_t)(2 * i) * 24 + 2 * j) * C_;
    const __nv_bfloat16* rr = g_r + (size_t)row * C_;
    int tid = threadIdx.x;
    int c = tid * 4;

    const __nv_bfloat162* rp = (const __nv_bfloat162*)(rr + c);
    float2 r01 = __bfloat1622float2(rp[0]);
    float2 r23 = __bfloat1622float2(rp[1]);
    float4 rv = make_float4(r01.x, r01.y, r23.x, r23.y);

    float4 x0 = *(const float4*)(xb + c);
    float4 x1 = *(const float4*)(xb + C_ + c);
    float4 x2 = *(const float4*)(xb + 24 * C_ + c);
    float4 x3 = *(const float4*)(xb + 25 * C_ + c);

    float s0 = rv.x * x0.x + rv.y * x0.y + rv.z * x0.z + rv.w * x0.w;
    float s1 = rv.x * x1.x + rv.y * x1.y + rv.z * x1.z + rv.w * x1.w;
    float s2 = rv.x * x2.x + rv.y * x2.y + rv.z * x2.z + rv.w * x2.w;
    float s3 = rv.x * x3.x + rv.y * x3.y + rv.z * x3.z + rv.w * x3.w;
    float qb = __bfloat162float(g_q[(size_t)row * MID_ + tid]) * bk[tid];

#pragma unroll
    for (int off = 16; off > 0; off >>= 1) {
        s0 += __shfl_down_sync(0xffffffff, s0, off);
        s1 += __shfl_down_sync(0xffffffff, s1, off);
        s2 += __shfl_down_sync(0xffffffff, s2, off);
        s3 += __shfl_down_sync(0xffffffff, s3, off);
        qb += __shfl_down_sync(0xffffffff, qb, off);
    }

    __shared__ float red[8][5];
    __shared__ float coef[4];
    int lane = tid & 31, warp = tid >> 5;
    if (lane == 0) {
        red[warp][0] = s0; red[warp][1] = s1; red[warp][2] = s2;
        red[warp][3] = s3; red[warp][4] = qb;
    }
    __syncthreads();
    if (tid == 0) {
        float S[5] = {0.f, 0.f, 0.f, 0.f, 0.f};
#pragma unroll
        for (int w = 0; w < 8; w++)
#pragma unroll
            for (int k = 0; k < 5; k++) S[k] += red[w][k];
        const float scale = 0.0625f;  // 1/sqrt(256)
        float l0 = (S[0] + S[4]) * scale;
        float l1 = (S[1] + S[4]) * scale;
        float l2 = (S[2] + S[4]) * scale;
        float l3 = (S[3] + S[4]) * scale;
        float m = fmaxf(fmaxf(l0, l1), fmaxf(l2, l3));
        float e0 = expf(l0 - m), e1 = expf(l1 - m);
        float e2 = expf(l2 - m), e3 = expf(l3 - m);
        float inv = 1.0f / (e0 + e1 + e2 + e3);
        coef[0] = 0.25f + e0 * inv;
        coef[1] = 0.25f + e1 * inv;
        coef[2] = 0.25f + e2 * inv;
        coef[3] = 0.25f + e3 * inv;
    }
    __syncthreads();
    float c0 = coef[0], c1 = coef[1], c2 = coef[2], c3 = coef[3];
    float4 o;
    o.x = c0 * x0.x + c1 * x1.x + c2 * x2.x + c3 * x3.x;
    o.y = c0 * x0.y + c1 * x1.y + c2 * x2.y + c3 * x3.y;
    o.z = c0 * x0.z + c1 * x1.z + c2 * x2.z + c3 * x3.z;
    o.w = c0 * x0.w + c1 * x1.w + c2 * x2.w + c3 * x3.w;
    *(float4*)(out + (size_t)row * C_ + c) = o;
}

// ---------------- launch ----------------
extern "C" void kernel_launch(void* const* d_in, const int* in_sizes, int n_in,
                              void* d_out, int out_size) {
    const float* x  = (const float*)d_in[0];  // [64, 576, 1024]
    const float* Wq = (const float*)d_in[1];  // [1024, 256]
    const float* bq = (const float*)d_in[2];  // [256]
    const float* Wk = (const float*)d_in[3];  // [1024, 256]
    const float* bk = (const float*)d_in[4];  // [256]
    float* out = (float*)d_out;               // [64, 144, 1024]

    __nv_bfloat16 *q, *r, *wt, *wkh;
    cudaGetSymbolAddress((void**)&q, g_q);
    cudaGetSymbolAddress((void**)&r, g_r);
    cudaGetSymbolAddress((void**)&wt, g_WT);
    cudaGetSymbolAddress((void**)&wkh, g_WkH);

    static int smem_set = 0;
    if (!smem_set) {
        cudaFuncSetAttribute(gemm1_fused,
                             cudaFuncAttributeMaxDynamicSharedMemorySize,
                             F_SMEM_BYTES);
        smem_set = 1;
    }

    transpose_w<<<dim3(32, 8), dim3(32, 8)>>>(Wq);
    cvt_wk<<<256, 256>>>(Wk);
    // q[9216,256] = pool2x2(x) @ Wq + bq  (BN=256 => x read exactly once)
    gemm1_fused<<<ROWS / 64, 256, F_SMEM_BYTES>>>(x, wt, bq, q);
    // r[9216,1024] = q @ Wk^T
    gemm2_bf16<<<dim3(C_ / 64, ROWS / 128), 128>>>(q, wkh, r, C_, MID_);
    attn_kernel<<<ROWS, 256>>>(x, bk, out);
}

// round 16
// speedup vs baseline: 1.0465x; 1.0397x over previous
#include <cuda_runtime.h>
#include <cuda_bf16.h>
#include <math.h>
#include <cstdint>

#define T_   64
#define P_   144
#define C_   1024
#define MID_ 256
#define ROWS (T_ * P_)   // 9216

#define TBUF_W 4096      // 128 rows x 32 words (per A or B buffer)
#define G_SMEM_BYTES ((4 * TBUF_W) * 4 + 512 + 128)

// ---------------- scratch (no allocations allowed) ----------------
__device__ __nv_bfloat16 g_pooled[ROWS * C_];  // 18.9 MB
__device__ __nv_bfloat16 g_q[ROWS * MID_];     //  4.7 MB
__device__ __nv_bfloat16 g_r[ROWS * C_];       // 18.9 MB
__device__ __nv_bfloat16 g_WT[MID_ * C_];      //  0.5 MB (Wq^T)
__device__ __nv_bfloat16 g_WkH[C_ * MID_];     //  0.5 MB (Wk)

__device__ __forceinline__ uint32_t smem_u32(const void* p) {
    uint32_t a;
    asm("{ .reg .u64 t; cvta.to.shared.u64 t, %1; cvt.u32.u64 %0, t; }"
        : "=r"(a) : "l"(p));
    return a;
}
__device__ __forceinline__ void cpasync16(uint32_t s, const void* g) {
    asm volatile("cp.async.cg.shared.global [%0], [%1], 16;" :: "r"(s), "l"(g));
}
#define CP_COMMIT() asm volatile("cp.async.commit_group;" ::: "memory")
#define CP_WAIT(N)  asm volatile("cp.async.wait_group %0;" :: "n"(N) : "memory")

__device__ __forceinline__ void mma_bf16(float& c0, float& c1, float& c2, float& c3,
                                         uint32_t a0, uint32_t a1, uint32_t a2, uint32_t a3,
                                         uint32_t b0, uint32_t b1) {
    asm volatile(
        "mma.sync.aligned.m16n8k16.row.col.f32.bf16.bf16.f32 "
        "{%0,%1,%2,%3}, {%4,%5,%6,%7}, {%8,%9}, {%0,%1,%2,%3};"
        : "+f"(c0), "+f"(c1), "+f"(c2), "+f"(c3)
        : "r"(a0), "r"(a1), "r"(a2), "r"(a3), "r"(b0), "r"(b1));
}

// ---------------- K1: 2x2 window average pool -> bf16 ----------------
__global__ void pool_kernel(const float* __restrict__ x) {
    int row = blockIdx.x;
    int t = row / P_, p = row % P_;
    int i = p / 12, j = p % 12;
    const float* base = x + ((size_t)t * 576 + (size_t)(2 * i) * 24 + 2 * j) * C_;
    int c = threadIdx.x * 4;
    float4 a = *(const float4*)(base + c);
    float4 b = *(const float4*)(base + C_ + c);
    float4 d = *(const float4*)(base + 24 * C_ + c);
    float4 e = *(const float4*)(base + 25 * C_ + c);
    __nv_bfloat162 o0 = __floats2bfloat162_rn(0.25f * ((a.x + b.x) + (d.x + e.x)),
                                              0.25f * ((a.y + b.y) + (d.y + e.y)));
    __nv_bfloat162 o1 = __floats2bfloat162_rn(0.25f * ((a.z + b.z) + (d.z + e.z)),
                                              0.25f * ((a.w + b.w) + (d.w + e.w)));
    uint2 pack = make_uint2(*(uint32_t*)&o0, *(uint32_t*)&o1);
    *(uint2*)(g_pooled + (size_t)row * C_ + c) = pack;
}

// ---------------- K2a: transpose Wq [1024,256] -> WT bf16 [256,1024] ----------
__global__ void transpose_w(const float* __restrict__ W) {
    __shared__ float s[32][33];
    int c0 = blockIdx.x * 32;
    int d0 = blockIdx.y * 32;
    int tx = threadIdx.x, ty = threadIdx.y;  // 32 x 8
#pragma unroll
    for (int u = 0; u < 32; u += 8)
        s[ty + u][tx] = W[(size_t)(c0 + ty + u) * MID_ + d0 + tx];
    __syncthreads();
#pragma unroll
    for (int u = 0; u < 32; u += 8)
        g_WT[(size_t)(d0 + ty + u) * C_ + c0 + tx] = __float2bfloat16(s[tx][ty + u]);
}

// ---------------- K2b: Wk -> bf16 copy ----------------
__global__ void cvt_wk(const float* __restrict__ Wk) {
    int i = blockIdx.x * 256 + threadIdx.x;
    float4 v = ((const float4*)Wk)[i];
    __nv_bfloat162 o0 = __floats2bfloat162_rn(v.x, v.y);
    __nv_bfloat162 o1 = __floats2bfloat162_rn(v.z, v.w);
    *(uint2*)(g_WkH + (size_t)i * 4) = make_uint2(*(uint32_t*)&o0, *(uint32_t*)&o1);
}

// ====== bf16 m16n8k16 GEMM: BM=128, BN=128, BK=64, 128 thr (4 warps 2m x 2n) ===
// Warp tile 64x64 (4 mt x 8 nt): 32 frag regs / 32 mma per k-step -> 1.0 reg/mma
// (vs 1.5 before) — cuts smem-crossbar traffic per MMA by 1.5x.
// D[M,N] = A[M,K] @ B[N,K]^T (+bias), bf16 in, f32 acc, bf16 out.
// cp.async 2-stage double buffer. Smem word (row,kw) at row*32 + (kw^((row&7)<<2)).
template <bool BIAS>
__global__ void __launch_bounds__(128)
gemm_bf16(const __nv_bfloat16* __restrict__ A, const __nv_bfloat16* __restrict__ B,
          const float* __restrict__ bias, __nv_bfloat16* __restrict__ Cout,
          const int N, const int K) {
    extern __shared__ uint32_t smem[];
    uint32_t* As0 = smem;                    // 2 x TBUF_W
    uint32_t* Bs0 = smem + 2 * TBUF_W;       // 2 x TBUF_W
    float* sBias = (float*)(smem + 4 * TBUF_W);

    const int tid = threadIdx.x;
    const int lane = tid & 31, wid = tid >> 5;
    const int warp_m = wid >> 1, warp_n = wid & 1;
    const int bm = blockIdx.y * 128, bn = blockIdx.x * 128;

    if (BIAS && tid < 128) sBias[tid] = bias[bn + tid];

    const int g = lane >> 2, tk = lane & 3;
    const int sw = g << 2;

    // staging: 8 x 16B columns over 64-elem K-chunk, 16-row strides (128 rows)
    const int lcol = tid & 7;     // 16B column
    const int lrow = tid >> 3;    // 0..15

    const __nv_bfloat16* ag = A + (size_t)(bm + lrow) * K + lcol * 8;
    const __nv_bfloat16* bg = B + (size_t)(bn + lrow) * K + lcol * 8;

    uint32_t soff[8];
#pragma unroll
    for (int it = 0; it < 8; it++) {
        int row = lrow + it * 16;
        soff[it] = 4u * (uint32_t)(row * 32 + ((lcol * 4) ^ ((row & 7) << 2)));
    }
    const uint32_t uA[2] = { smem_u32(As0), smem_u32(As0 + TBUF_W) };
    const uint32_t uB[2] = { smem_u32(Bs0), smem_u32(Bs0 + TBUF_W) };

    float acc[4][8][4];
#pragma unroll
    for (int i = 0; i < 4; i++)
#pragma unroll
        for (int j = 0; j < 8; j++)
#pragma unroll
            for (int f = 0; f < 4; f++) acc[i][j][f] = 0.0f;

#define STAGE(BUF, K0)                                                         \
    {                                                                          \
        const int _k0 = (K0);                                                  \
        const uint32_t _ua = uA[BUF], _ub = uB[BUF];                           \
        _Pragma("unroll")                                                      \
        for (int it = 0; it < 8; it++) {                                       \
            cpasync16(_ua + soff[it], ag + (size_t)it * 16 * K + _k0);         \
            cpasync16(_ub + soff[it], bg + (size_t)it * 16 * K + _k0);         \
        }                                                                      \
    }

    STAGE(0, 0)
    CP_COMMIT();

    const int nch = K >> 6;   // 64 elems per chunk
    for (int ck = 0; ck < nch; ck++) {
        const int buf = ck & 1;
        const bool more = (ck + 1) < nch;
        if (more) {
            STAGE(buf ^ 1, (ck + 1) << 6)
            CP_COMMIT();
            CP_WAIT(1);
        } else {
            CP_WAIT(0);
        }
        __syncthreads();

        const uint32_t* Ab = As0 + buf * TBUF_W;
        const uint32_t* Bb = Bs0 + buf * TBUF_W;
#pragma unroll
        for (int ks = 0; ks < 4; ks++) {
            const int kx  = (ks * 8 + tk) ^ sw;
            const int kx4 = kx ^ 4;

            uint32_t af[4][4];
#pragma unroll
            for (int mt = 0; mt < 4; mt++) {
                int r = warp_m * 64 + mt * 16 + g;
                af[mt][0] = Ab[r * 32 + kx];
                af[mt][1] = Ab[(r + 8) * 32 + kx];
                af[mt][2] = Ab[r * 32 + kx4];
                af[mt][3] = Ab[(r + 8) * 32 + kx4];
            }
            uint32_t bf[8][2];
#pragma unroll
            for (int nt = 0; nt < 8; nt++) {
                int n = warp_n * 64 + nt * 8 + g;
                bf[nt][0] = Bb[n * 32 + kx];
                bf[nt][1] = Bb[n * 32 + kx4];
            }
#pragma unroll
            for (int mt = 0; mt < 4; mt++)
#pragma unroll
                for (int nt = 0; nt < 8; nt++)
                    mma_bf16(acc[mt][nt][0], acc[mt][nt][1],
                             acc[mt][nt][2], acc[mt][nt][3],
                             af[mt][0], af[mt][1], af[mt][2], af[mt][3],
                             bf[nt][0], bf[nt][1]);
        }
        __syncthreads();
    }
#undef STAGE

    // epilogue: bf16 out
#pragma unroll
    for (int mt = 0; mt < 4; mt++) {
#pragma unroll
        for (int nt = 0; nt < 8; nt++) {
            int r = bm + warp_m * 64 + mt * 16 + g;
            int cbase = warp_n * 64 + nt * 8 + tk * 2;
            float b0 = BIAS ? sBias[cbase] : 0.0f;
            float b1 = BIAS ? sBias[cbase + 1] : 0.0f;
            int cg = bn + cbase;
            *(__nv_bfloat162*)(Cout + (size_t)r * N + cg) =
                __floats2bfloat162_rn(acc[mt][nt][0] + b0, acc[mt][nt][1] + b1);
            *(__nv_bfloat162*)(Cout + (size_t)(r + 8) * N + cg) =
                __floats2bfloat162_rn(acc[mt][nt][2] + b0, acc[mt][nt][3] + b1);
        }
    }
}

// ---------------- K5: attention dots + softmax + weighted epilogue ----------------
__global__ void attn_kernel(const float* __restrict__ x, const float* __restrict__ bk,
                            float* __restrict__ out) {
    int row = blockIdx.x;
    int t = row / P_, p = row % P_;
    int i = p / 12, j = p % 12;
    const float* xb = x + ((size_t)t * 576 + (size_t)(2 * i) * 24 + 2 * j) * C_;
    const __nv_bfloat16* rr = g_r + (size_t)row * C_;
    int tid = threadIdx.x;
    int c = tid * 4;

    const __nv_bfloat162* rp = (const __nv_bfloat162*)(rr + c);
    float2 r01 = __bfloat1622float2(rp[0]);
    float2 r23 = __bfloat1622float2(rp[1]);
    float4 rv = make_float4(r01.x, r01.y, r23.x, r23.y);

    float4 x0 = *(const float4*)(xb + c);
    float4 x1 = *(const float4*)(xb + C_ + c);
    float4 x2 = *(const float4*)(xb + 24 * C_ + c);
    float4 x3 = *(const float4*)(xb + 25 * C_ + c);

    float s0 = rv.x * x0.x + rv.y * x0.y + rv.z * x0.z + rv.w * x0.w;
    float s1 = rv.x * x1.x + rv.y * x1.y + rv.z * x1.z + rv.w * x1.w;
    float s2 = rv.x * x2.x + rv.y * x2.y + rv.z * x2.z + rv.w * x2.w;
    float s3 = rv.x * x3.x + rv.y * x3.y + rv.z * x3.z + rv.w * x3.w;
    float qb = __bfloat162float(g_q[(size_t)row * MID_ + tid]) * bk[tid];

#pragma unroll
    for (int off = 16; off > 0; off >>= 1) {
        s0 += __shfl_down_sync(0xffffffff, s0, off);
        s1 += __shfl_down_sync(0xffffffff, s1, off);
        s2 += __shfl_down_sync(0xffffffff, s2, off);
        s3 += __shfl_down_sync(0xffffffff, s3, off);
        qb += __shfl_down_sync(0xffffffff, qb, off);
    }

    __shared__ float red[8][5];
    __shared__ float coef[4];
    int lane = tid & 31, warp = tid >> 5;
    if (lane == 0) {
        red[warp][0] = s0; red[warp][1] = s1; red[warp][2] = s2;
        red[warp][3] = s3; red[warp][4] = qb;
    }
    __syncthreads();
    if (tid == 0) {
        float S[5] = {0.f, 0.f, 0.f, 0.f, 0.f};
#pragma unroll
        for (int w = 0; w < 8; w++)
#pragma unroll
            for (int k = 0; k < 5; k++) S[k] += red[w][k];
        const float scale = 0.0625f;  // 1/sqrt(256)
        float l0 = (S[0] + S[4]) * scale;
        float l1 = (S[1] + S[4]) * scale;
        float l2 = (S[2] + S[4]) * scale;
        float l3 = (S[3] + S[4]) * scale;
        float m = fmaxf(fmaxf(l0, l1), fmaxf(l2, l3));
        float e0 = expf(l0 - m), e1 = expf(l1 - m);
        float e2 = expf(l2 - m), e3 = expf(l3 - m);
        float inv = 1.0f / (e0 + e1 + e2 + e3);
        coef[0] = 0.25f + e0 * inv;
        coef[1] = 0.25f + e1 * inv;
        coef[2] = 0.25f + e2 * inv;
        coef[3] = 0.25f + e3 * inv;
    }
    __syncthreads();
    float c0 = coef[0], c1 = coef[1], c2 = coef[2], c3 = coef[3];
    float4 o;
    o.x = c0 * x0.x + c1 * x1.x + c2 * x2.x + c3 * x3.x;
    o.y = c0 * x0.y + c1 * x1.y + c2 * x2.y + c3 * x3.y;
    o.z = c0 * x0.z + c1 * x1.z + c2 * x2.z + c3 * x3.z;
    o.w = c0 * x0.w + c1 * x1.w + c2 * x2.w + c3 * x3.w;
    *(float4*)(out + (size_t)row * C_ + c) = o;
}

// ---------------- launch ----------------
extern "C" void kernel_launch(void* const* d_in, const int* in_sizes, int n_in,
                              void* d_out, int out_size) {
    const float* x  = (const float*)d_in[0];  // [64, 576, 1024]
    const float* Wq = (const float*)d_in[1];  // [1024, 256]
    const float* bq = (const float*)d_in[2];  // [256]
    const float* Wk = (const float*)d_in[3];  // [1024, 256]
    const float* bk = (const float*)d_in[4];  // [256]
    float* out = (float*)d_out;               // [64, 144, 1024]

    __nv_bfloat16 *pooled, *q, *r, *wt, *wkh;
    cudaGetSymbolAddress((void**)&pooled, g_pooled);
    cudaGetSymbolAddress((void**)&q, g_q);
    cudaGetSymbolAddress((void**)&r, g_r);
    cudaGetSymbolAddress((void**)&wt, g_WT);
    cudaGetSymbolAddress((void**)&wkh, g_WkH);

    static int smem_set = 0;
    if (!smem_set) {
        cudaFuncSetAttribute(gemm_bf16<true>,
                             cudaFuncAttributeMaxDynamicSharedMemorySize, G_SMEM_BYTES);
        cudaFuncSetAttribute(gemm_bf16<false>,
                             cudaFuncAttributeMaxDynamicSharedMemorySize, G_SMEM_BYTES);
        smem_set = 1;
    }

    pool_kernel<<<ROWS, 256>>>(x);
    transpose_w<<<dim3(32, 8), dim3(32, 8)>>>(Wq);
    cvt_wk<<<256, 256>>>(Wk);
    // q[9216,256] = pooled @ Wq + bq   (BN=128 -> grid 2 x 72)
    gemm_bf16<true><<<dim3(MID_ / 128, ROWS / 128), 128, G_SMEM_BYTES>>>(
        pooled, wt, bq, q, MID_, C_);
    // r[9216,1024] = q @ Wk^T          (BN=128 -> grid 8 x 72)
    gemm_bf16<false><<<dim3(C_ / 128, ROWS / 128), 128, G_SMEM_BYTES>>>(
        q, wkh, nullptr, r, C_, MID_);
    attn_kernel<<<ROWS, 256>>>(x, bk, out);
}